// round 2
// baseline (speedup 1.0000x reference)
#include <cuda_runtime.h>
#include <math.h>

#define N_NODES 100000
#define N_EDGES 1600000
#define F_IN    500
#define F_HID   64
#define F_OUT   40

// ---------------- scratch (static device globals; no allocations) ----------
__device__ float g_xw1[N_NODES * F_HID];     // X @ W1
__device__ float g_h  [N_NODES * F_HID];     // relu(conv1)
__device__ float g_xw2[N_NODES * F_OUT];     // h @ W2
__device__ float g_dinv[N_NODES];
__device__ int   g_deg [N_NODES];
__device__ int   g_cnt [N_NODES];
__device__ int   g_rowptr[N_NODES + 1];
__device__ int   g_col[N_EDGES];
__device__ int   g_blocksum[128];
__device__ int   g_blockoff[128];

// ---------------- graph preprocessing --------------------------------------
__global__ void k_zero(int n) {
    int i = blockIdx.x * blockDim.x + threadIdx.x;
    if (i < n) { g_deg[i] = 0; g_cnt[i] = 0; }
}

// edge_index is int32 (JAX downcasts int64 without x64 mode)
__global__ void k_deg(const int* __restrict__ ei, int E) {
    int i = blockIdx.x * blockDim.x + threadIdx.x;
    if (i < E) {
        int dst = ei[E + i];
        if (dst >= 0 && dst < N_NODES) atomicAdd(&g_deg[dst], 1);
    }
}

__global__ void k_dinv(int n) {
    int i = blockIdx.x * blockDim.x + threadIdx.x;
    if (i < n) g_dinv[i] = rsqrtf((float)(g_deg[i] + 1));  // +1 self loop, always > 0
}

// block-local exclusive scan of g_deg into g_rowptr, block totals to g_blocksum
__global__ void k_scan_blocks(int n) {
    __shared__ int buf[1024];
    int tid = threadIdx.x;
    int gid = blockIdx.x * 1024 + tid;
    int v = (gid < n) ? g_deg[gid] : 0;
    buf[tid] = v;
    __syncthreads();
    #pragma unroll
    for (int off = 1; off < 1024; off <<= 1) {
        int t = (tid >= off) ? buf[tid - off] : 0;
        __syncthreads();
        buf[tid] += t;
        __syncthreads();
    }
    if (gid < n) g_rowptr[gid] = buf[tid] - v;  // exclusive
    if (tid == 1023) g_blocksum[blockIdx.x] = buf[1023];
}

__global__ void k_scan_partials(int nb) {
    __shared__ int buf[128];
    int tid = threadIdx.x;  // 128 threads
    int v = (tid < nb) ? g_blocksum[tid] : 0;
    buf[tid] = v;
    __syncthreads();
    #pragma unroll
    for (int off = 1; off < 128; off <<= 1) {
        int t = (tid >= off) ? buf[tid - off] : 0;
        __syncthreads();
        buf[tid] += t;
        __syncthreads();
    }
    g_blockoff[tid] = buf[tid] - v;  // exclusive
}

__global__ void k_scan_add(int n, int E) {
    int gid = blockIdx.x * blockDim.x + threadIdx.x;
    if (gid < n) g_rowptr[gid] += g_blockoff[gid >> 10];
    if (gid == 0) g_rowptr[n] = E;
}

__global__ void k_fill_col(const int* __restrict__ ei, int E) {
    int i = blockIdx.x * blockDim.x + threadIdx.x;
    if (i < E) {
        int src = ei[i];
        int dst = ei[E + i];
        if (dst >= 0 && dst < N_NODES && src >= 0 && src < N_NODES) {
            int p = g_rowptr[dst] + atomicAdd(&g_cnt[dst], 1);
            g_col[p] = src;
        }
    }
}

// ---------------- GEMM1: X[M,500] @ W1[500,64] -> g_xw1 --------------------
// 64x64 tile, BK=32, 256 threads, 4x4 register blocking
__global__ __launch_bounds__(256) void k_gemm1(const float* __restrict__ X,
                                               const float* __restrict__ W,
                                               int M) {
    __shared__ float As[32][64];
    __shared__ float Bs[32][64];
    int tid = threadIdx.x;
    int tx = tid & 15, ty = tid >> 4;
    int row0 = blockIdx.x * 64;
    float acc[4][4] = {};

    for (int k0 = 0; k0 < F_IN; k0 += 32) {
        // A tile: 64 rows x 32 k  (512 float4, 2 per thread)
        #pragma unroll
        for (int i = 0; i < 2; i++) {
            int idx = tid + i * 256;
            int r = idx >> 3;          // 0..63
            int kq = idx & 7;          // 0..7 (x4)
            int k = k0 + kq * 4;
            int grow = row0 + r;
            float4 v = make_float4(0.f, 0.f, 0.f, 0.f);
            if (grow < M && k < F_IN)
                v = *(const float4*)&X[(size_t)grow * F_IN + k];
            As[kq * 4 + 0][r] = v.x;
            As[kq * 4 + 1][r] = v.y;
            As[kq * 4 + 2][r] = v.z;
            As[kq * 4 + 3][r] = v.w;
        }
        // B tile: 32 k x 64 n
        #pragma unroll
        for (int i = 0; i < 2; i++) {
            int idx = tid + i * 256;
            int kr = idx >> 4;         // 0..31
            int nq = idx & 15;         // x4
            int k = k0 + kr;
            float4 v = make_float4(0.f, 0.f, 0.f, 0.f);
            if (k < F_IN)
                v = *(const float4*)&W[(size_t)k * F_HID + nq * 4];
            *(float4*)&Bs[kr][nq * 4] = v;
        }
        __syncthreads();
        #pragma unroll
        for (int kk = 0; kk < 32; kk++) {
            float a[4], b[4];
            #pragma unroll
            for (int i = 0; i < 4; i++) a[i] = As[kk][ty * 4 + i];
            #pragma unroll
            for (int j = 0; j < 4; j++) b[j] = Bs[kk][tx * 4 + j];
            #pragma unroll
            for (int i = 0; i < 4; i++)
                #pragma unroll
                for (int j = 0; j < 4; j++)
                    acc[i][j] += a[i] * b[j];
        }
        __syncthreads();
    }
    #pragma unroll
    for (int i = 0; i < 4; i++) {
        int grow = row0 + ty * 4 + i;
        if (grow < M)
            *(float4*)&g_xw1[(size_t)grow * F_HID + tx * 4] =
                make_float4(acc[i][0], acc[i][1], acc[i][2], acc[i][3]);
    }
}

// ---------------- agg layer 1 (F=64) + bias + relu -> g_h ------------------
// one warp per node; warp-cooperative neighbor fetch, float2 per lane
__global__ __launch_bounds__(256) void k_agg1(const float* __restrict__ b1, int N) {
    int warp = (blockIdx.x * blockDim.x + threadIdx.x) >> 5;
    int lane = threadIdx.x & 31;
    if (warp >= N) return;
    int n = warp;
    int start = g_rowptr[n], end = g_rowptr[n + 1];

    float ax = 0.f, ay = 0.f;
    for (int e0 = start; e0 < end; e0 += 32) {
        int idx = e0 + lane;
        int s = 0; float w = 0.f;
        if (idx < end) { s = g_col[idx]; w = g_dinv[s]; }
        int cnt = min(32, end - e0);
        for (int j = 0; j < cnt; j++) {
            int   sj = __shfl_sync(0xffffffffu, s, j);
            float wj = __shfl_sync(0xffffffffu, w, j);
            float2 v = *(const float2*)&g_xw1[(size_t)sj * F_HID + lane * 2];
            ax += wj * v.x;
            ay += wj * v.y;
        }
    }
    float dn = g_dinv[n];
    float2 sv = *(const float2*)&g_xw1[(size_t)n * F_HID + lane * 2];
    float ox = dn * (ax + dn * sv.x) + b1[lane * 2];
    float oy = dn * (ay + dn * sv.y) + b1[lane * 2 + 1];
    ox = fmaxf(ox, 0.f);
    oy = fmaxf(oy, 0.f);
    *(float2*)&g_h[(size_t)n * F_HID + lane * 2] = make_float2(ox, oy);
}

// ---------------- GEMM2: g_h[M,64] @ W2[64,40] -> g_xw2 --------------------
__global__ __launch_bounds__(256) void k_gemm2(const float* __restrict__ W2, int M) {
    __shared__ float Ws[F_HID * F_OUT];   // 2560
    __shared__ float hrow[8][F_HID];
    int tid = threadIdx.x;
    for (int i = tid; i < F_HID * F_OUT; i += 256) Ws[i] = W2[i];
    __syncthreads();
    int warp = tid >> 5, lane = tid & 31;
    int gw = blockIdx.x * 8 + warp;
    int stride = gridDim.x * 8;
    for (int r = gw; r < M; r += stride) {
        float2 hv = *(const float2*)&g_h[(size_t)r * F_HID + lane * 2];
        hrow[warp][lane * 2]     = hv.x;
        hrow[warp][lane * 2 + 1] = hv.y;
        __syncwarp();
        float a0 = 0.f, a1 = 0.f;
        #pragma unroll
        for (int k = 0; k < F_HID; k++) {
            float h = hrow[warp][k];
            a0 += h * Ws[k * F_OUT + lane];
            if (lane < 8) a1 += h * Ws[k * F_OUT + lane + 32];
        }
        g_xw2[(size_t)r * F_OUT + lane] = a0;
        if (lane < 8) g_xw2[(size_t)r * F_OUT + lane + 32] = a1;
        __syncwarp();
    }
}

// ------- agg layer 2 (F=40) + bias + fused log_softmax -> d_out ------------
// out layout: [0, N*40) log_softmax ; optionally [logits_off, logits_off+N*40) logits
__global__ __launch_bounds__(256) void k_agg2(const float* __restrict__ b2,
                                              float* __restrict__ out, int N,
                                              long long logits_off) {
    int warp = (blockIdx.x * blockDim.x + threadIdx.x) >> 5;
    int lane = threadIdx.x & 31;
    if (warp >= N) return;
    int n = warp;
    bool act = lane < 20;   // lanes 0..19 each own 2 of the 40 features
    int start = g_rowptr[n], end = g_rowptr[n + 1];

    float ax = 0.f, ay = 0.f;
    for (int e0 = start; e0 < end; e0 += 32) {
        int idx = e0 + lane;
        int s = 0; float w = 0.f;
        if (idx < end) { s = g_col[idx]; w = g_dinv[s]; }
        int cnt = min(32, end - e0);
        for (int j = 0; j < cnt; j++) {
            int   sj = __shfl_sync(0xffffffffu, s, j);
            float wj = __shfl_sync(0xffffffffu, w, j);
            if (act) {
                float2 v = *(const float2*)&g_xw2[(size_t)sj * F_OUT + lane * 2];
                ax += wj * v.x;
                ay += wj * v.y;
            }
        }
    }
    float dn = g_dinv[n];
    float o0 = 0.f, o1 = 0.f;
    if (act) {
        float2 sv = *(const float2*)&g_xw2[(size_t)n * F_OUT + lane * 2];
        o0 = dn * (ax + dn * sv.x) + b2[lane * 2];
        o1 = dn * (ay + dn * sv.y) + b2[lane * 2 + 1];
    }
    // warp log-softmax over the 40 values
    float m = act ? fmaxf(o0, o1) : -3.402823e38f;
    #pragma unroll
    for (int off = 16; off > 0; off >>= 1)
        m = fmaxf(m, __shfl_xor_sync(0xffffffffu, m, off));
    float s = act ? (expf(o0 - m) + expf(o1 - m)) : 0.f;
    #pragma unroll
    for (int off = 16; off > 0; off >>= 1)
        s += __shfl_xor_sync(0xffffffffu, s, off);
    float lse = logf(s) + m;
    if (act) {
        size_t base = (size_t)n * F_OUT + lane * 2;
        out[base]     = o0 - lse;              // log_softmax
        out[base + 1] = o1 - lse;
        if (logits_off > 0) {
            out[(size_t)logits_off + base]     = o0;  // logits
            out[(size_t)logits_off + base + 1] = o1;
        }
    }
}

// ---------------------------------------------------------------------------
extern "C" void kernel_launch(void* const* d_in, const int* in_sizes, int n_in,
                              void* d_out, int out_size) {
    const float* x  = (const float*)d_in[0];
    const int*   ei = (const int*)d_in[1];     // int32 (JAX x64 disabled)
    const float* W1 = (const float*)d_in[2];
    const float* b1 = (const float*)d_in[3];
    const float* W2 = (const float*)d_in[4];
    const float* b2 = (const float*)d_in[5];
    float* out = (float*)d_out;

    int N = in_sizes[0] / F_IN;    // 100000
    int E = in_sizes[1] / 2;       // 1600000
    int NB = (N + 1023) / 1024;    // 98 scan blocks

    // second tuple element (logits) only if the output buffer holds both
    long long logits_off = ((long long)out_size >= 2LL * N * F_OUT)
                         ? (long long)N * F_OUT : 0;

    // graph preprocessing
    k_zero<<<(N + 255) / 256, 256>>>(N);
    k_deg<<<(E + 255) / 256, 256>>>(ei, E);
    k_dinv<<<(N + 255) / 256, 256>>>(N);
    k_scan_blocks<<<NB, 1024>>>(N);
    k_scan_partials<<<1, 128>>>(NB);
    k_scan_add<<<(N + 255) / 256, 256>>>(N, E);
    k_fill_col<<<(E + 255) / 256, 256>>>(ei, E);

    // layer 1
    k_gemm1<<<(N + 63) / 64, 256>>>(x, W1, N);
    k_agg1<<<(N * 32 + 255) / 256, 256>>>(b1, N);

    // layer 2
    k_gemm2<<<4096, 256>>>(W2, N);
    k_agg2<<<(N * 32 + 255) / 256, 256>>>(b2, out, N, logits_off);
}

// round 3
// speedup vs baseline: 1.2248x; 1.2248x over previous
#include <cuda_runtime.h>
#include <math.h>
#include <stdint.h>

#define N_NODES 100000
#define N_EDGES 1600000
#define F_IN    500
#define F_HID   64
#define F_OUT   40

// ---------------- scratch (static device globals; no allocations) ----------
__device__ float g_xw1[N_NODES * F_HID];     // X @ W1
__device__ float g_h  [N_NODES * F_HID];     // relu(conv1)
__device__ float g_xw2[N_NODES * F_OUT];     // h @ W2
__device__ float g_dinv[N_NODES];
__device__ int   g_deg [N_NODES];
__device__ int   g_cnt [N_NODES];
__device__ int   g_rowptr[N_NODES + 1];
__device__ int   g_col[N_EDGES];
__device__ int   g_blocksum[128];
__device__ int   g_blockoff[128];

// ---------------- graph preprocessing --------------------------------------
__global__ void k_zero(int n) {
    int i = blockIdx.x * blockDim.x + threadIdx.x;
    if (i < n) { g_deg[i] = 0; g_cnt[i] = 0; }
}

// edge_index is int32 (JAX downcasts int64 without x64 mode)
__global__ void k_deg(const int* __restrict__ ei, int E) {
    int i = blockIdx.x * blockDim.x + threadIdx.x;
    if (i < E) {
        int dst = ei[E + i];
        if (dst >= 0 && dst < N_NODES) atomicAdd(&g_deg[dst], 1);
    }
}

__global__ void k_dinv(int n) {
    int i = blockIdx.x * blockDim.x + threadIdx.x;
    if (i < n) g_dinv[i] = rsqrtf((float)(g_deg[i] + 1));  // +1 self loop, always > 0
}

// block-local exclusive scan of g_deg into g_rowptr, block totals to g_blocksum
__global__ void k_scan_blocks(int n) {
    __shared__ int buf[1024];
    int tid = threadIdx.x;
    int gid = blockIdx.x * 1024 + tid;
    int v = (gid < n) ? g_deg[gid] : 0;
    buf[tid] = v;
    __syncthreads();
    #pragma unroll
    for (int off = 1; off < 1024; off <<= 1) {
        int t = (tid >= off) ? buf[tid - off] : 0;
        __syncthreads();
        buf[tid] += t;
        __syncthreads();
    }
    if (gid < n) g_rowptr[gid] = buf[tid] - v;  // exclusive
    if (tid == 1023) g_blocksum[blockIdx.x] = buf[1023];
}

__global__ void k_scan_partials(int nb) {
    __shared__ int buf[128];
    int tid = threadIdx.x;  // 128 threads
    int v = (tid < nb) ? g_blocksum[tid] : 0;
    buf[tid] = v;
    __syncthreads();
    #pragma unroll
    for (int off = 1; off < 128; off <<= 1) {
        int t = (tid >= off) ? buf[tid - off] : 0;
        __syncthreads();
        buf[tid] += t;
        __syncthreads();
    }
    g_blockoff[tid] = buf[tid] - v;  // exclusive
}

__global__ void k_scan_add(int n, int E) {
    int gid = blockIdx.x * blockDim.x + threadIdx.x;
    if (gid < n) g_rowptr[gid] += g_blockoff[gid >> 10];
    if (gid == 0) g_rowptr[n] = E;
}

__global__ void k_fill_col(const int* __restrict__ ei, int E) {
    int i = blockIdx.x * blockDim.x + threadIdx.x;
    if (i < E) {
        int src = ei[i];
        int dst = ei[E + i];
        if (dst >= 0 && dst < N_NODES && src >= 0 && src < N_NODES) {
            int p = g_rowptr[dst] + atomicAdd(&g_cnt[dst], 1);
            g_col[p] = src;
        }
    }
}

// ---------------- GEMM1 (tf32 tensor cores) --------------------------------
// X[M,500] @ W1[500,64] -> g_xw1.  BM=128, BN=64, BK=32, 256 threads.
// 8 warps in 4x2; each warp computes 32x32 via m16n8k8 tf32 mma.

__device__ __forceinline__ uint32_t f2tf32(float x) {
    uint32_t r;
    asm("cvt.rna.tf32.f32 %0, %1;" : "=r"(r) : "f"(x));
    return r;
}

__device__ __forceinline__ void mma_tf32(float* c, const uint32_t* a, const uint32_t* b) {
    asm volatile(
        "mma.sync.aligned.m16n8k8.row.col.f32.tf32.tf32.f32 "
        "{%0,%1,%2,%3}, {%4,%5,%6,%7}, {%8,%9}, {%0,%1,%2,%3};"
        : "+f"(c[0]), "+f"(c[1]), "+f"(c[2]), "+f"(c[3])
        : "r"(a[0]), "r"(a[1]), "r"(a[2]), "r"(a[3]), "r"(b[0]), "r"(b[1]));
}

#define G1_BM 128
#define G1_BK 32
#define G1_SA 137   // As stride (k-major): conflict-free stores, ~2-way frag loads
#define G1_SB 72    // Bs stride: conflict-free both ways

__global__ __launch_bounds__(256) void k_gemm1_tf32(const float* __restrict__ X,
                                                    const float* __restrict__ W,
                                                    int M) {
    __shared__ uint32_t As[G1_BK * G1_SA];   // As[k][m]
    __shared__ uint32_t Bs[G1_BK * G1_SB];   // Bs[k][n]
    int tid  = threadIdx.x;
    int lane = tid & 31, warp = tid >> 5;
    int warp_m = warp >> 1;        // 0..3 -> 32 rows each
    int warp_n = warp & 1;         // 0..1 -> 32 cols each
    int g  = lane >> 2;            // 0..7
    int tg = lane & 3;             // 0..3
    int row0 = blockIdx.x * G1_BM;

    float c[2][4][4] = {};         // [mfrag][nfrag][4]

    for (int k0 = 0; k0 < 512; k0 += G1_BK) {
        // ---- A tile: 128 rows x 32 k (coalesced float4 loads) ----
        #pragma unroll
        for (int i = 0; i < 4; i++) {
            int s  = tid + i * 256;      // 0..1023
            int r  = s >> 3;             // 0..127
            int kq = s & 7;              // float4 slot in k
            int k  = k0 + kq * 4;
            int grow = row0 + r;
            float4 v = make_float4(0.f, 0.f, 0.f, 0.f);
            if (grow < M && k + 4 <= F_IN)
                v = *(const float4*)&X[(size_t)grow * F_IN + k];
            As[(kq * 4 + 0) * G1_SA + r] = f2tf32(v.x);
            As[(kq * 4 + 1) * G1_SA + r] = f2tf32(v.y);
            As[(kq * 4 + 2) * G1_SA + r] = f2tf32(v.z);
            As[(kq * 4 + 3) * G1_SA + r] = f2tf32(v.w);
        }
        // ---- B tile: 32 k x 64 n ----
        #pragma unroll
        for (int i = 0; i < 2; i++) {
            int s  = tid + i * 256;      // 0..511
            int kr = s >> 4;             // 0..31
            int nq = s & 15;             // float4 slot in n
            int k  = k0 + kr;
            float4 v = make_float4(0.f, 0.f, 0.f, 0.f);
            if (k < F_IN)
                v = *(const float4*)&W[(size_t)k * F_HID + nq * 4];
            uint4 u;
            u.x = f2tf32(v.x); u.y = f2tf32(v.y);
            u.z = f2tf32(v.z); u.w = f2tf32(v.w);
            *(uint4*)&Bs[kr * G1_SB + nq * 4] = u;
        }
        __syncthreads();

        int m0 = warp_m * 32;
        int n0 = warp_n * 32;
        #pragma unroll
        for (int kb = 0; kb < G1_BK; kb += 8) {
            uint32_t a[2][4], b[4][2];
            #pragma unroll
            for (int mf = 0; mf < 2; mf++) {
                int r = m0 + mf * 16 + g;
                a[mf][0] = As[(kb + tg)     * G1_SA + r];
                a[mf][1] = As[(kb + tg)     * G1_SA + r + 8];
                a[mf][2] = As[(kb + tg + 4) * G1_SA + r];
                a[mf][3] = As[(kb + tg + 4) * G1_SA + r + 8];
            }
            #pragma unroll
            for (int nf = 0; nf < 4; nf++) {
                int n = n0 + nf * 8 + g;
                b[nf][0] = Bs[(kb + tg)     * G1_SB + n];
                b[nf][1] = Bs[(kb + tg + 4) * G1_SB + n];
            }
            #pragma unroll
            for (int mf = 0; mf < 2; mf++)
                #pragma unroll
                for (int nf = 0; nf < 4; nf++)
                    mma_tf32(c[mf][nf], a[mf], b[nf]);
        }
        __syncthreads();
    }

    // ---- epilogue: c -> g_xw1 ----
    #pragma unroll
    for (int mf = 0; mf < 2; mf++) {
        int r0 = row0 + warp_m * 32 + mf * 16 + g;
        int r1 = r0 + 8;
        #pragma unroll
        for (int nf = 0; nf < 4; nf++) {
            int col = warp_n * 32 + nf * 8 + tg * 2;
            if (r0 < M)
                *(float2*)&g_xw1[(size_t)r0 * F_HID + col] =
                    make_float2(c[mf][nf][0], c[mf][nf][1]);
            if (r1 < M)
                *(float2*)&g_xw1[(size_t)r1 * F_HID + col] =
                    make_float2(c[mf][nf][2], c[mf][nf][3]);
        }
    }
}

// ---------------- agg layer 1 (F=64) + bias + relu -> g_h ------------------
__global__ __launch_bounds__(256) void k_agg1(const float* __restrict__ b1, int N) {
    int warp = (blockIdx.x * blockDim.x + threadIdx.x) >> 5;
    int lane = threadIdx.x & 31;
    if (warp >= N) return;
    int n = warp;
    int start = g_rowptr[n], end = g_rowptr[n + 1];

    float ax = 0.f, ay = 0.f;
    for (int e0 = start; e0 < end; e0 += 32) {
        int idx = e0 + lane;
        int s = 0; float w = 0.f;
        if (idx < end) { s = g_col[idx]; w = g_dinv[s]; }
        int cnt = min(32, end - e0);
        for (int j = 0; j < cnt; j++) {
            int   sj = __shfl_sync(0xffffffffu, s, j);
            float wj = __shfl_sync(0xffffffffu, w, j);
            float2 v = *(const float2*)&g_xw1[(size_t)sj * F_HID + lane * 2];
            ax += wj * v.x;
            ay += wj * v.y;
        }
    }
    float dn = g_dinv[n];
    float2 sv = *(const float2*)&g_xw1[(size_t)n * F_HID + lane * 2];
    float ox = dn * (ax + dn * sv.x) + b1[lane * 2];
    float oy = dn * (ay + dn * sv.y) + b1[lane * 2 + 1];
    ox = fmaxf(ox, 0.f);
    oy = fmaxf(oy, 0.f);
    *(float2*)&g_h[(size_t)n * F_HID + lane * 2] = make_float2(ox, oy);
}

// ---------------- GEMM2: g_h[M,64] @ W2[64,40] -> g_xw2 --------------------
__global__ __launch_bounds__(256) void k_gemm2(const float* __restrict__ W2, int M) {
    __shared__ float Ws[F_HID * F_OUT];   // 2560
    __shared__ float hrow[8][F_HID];
    int tid = threadIdx.x;
    for (int i = tid; i < F_HID * F_OUT; i += 256) Ws[i] = W2[i];
    __syncthreads();
    int warp = tid >> 5, lane = tid & 31;
    int gw = blockIdx.x * 8 + warp;
    int stride = gridDim.x * 8;
    for (int r = gw; r < M; r += stride) {
        float2 hv = *(const float2*)&g_h[(size_t)r * F_HID + lane * 2];
        hrow[warp][lane * 2]     = hv.x;
        hrow[warp][lane * 2 + 1] = hv.y;
        __syncwarp();
        float a0 = 0.f, a1 = 0.f;
        #pragma unroll
        for (int k = 0; k < F_HID; k++) {
            float h = hrow[warp][k];
            a0 += h * Ws[k * F_OUT + lane];
            if (lane < 8) a1 += h * Ws[k * F_OUT + lane + 32];
        }
        g_xw2[(size_t)r * F_OUT + lane] = a0;
        if (lane < 8) g_xw2[(size_t)r * F_OUT + lane + 32] = a1;
        __syncwarp();
    }
}

// ------- agg layer 2 (F=40) + bias + fused log_softmax -> d_out ------------
__global__ __launch_bounds__(256) void k_agg2(const float* __restrict__ b2,
                                              float* __restrict__ out, int N,
                                              long long logits_off) {
    int warp = (blockIdx.x * blockDim.x + threadIdx.x) >> 5;
    int lane = threadIdx.x & 31;
    if (warp >= N) return;
    int n = warp;
    bool act = lane < 20;   // lanes 0..19 each own 2 of the 40 features
    int start = g_rowptr[n], end = g_rowptr[n + 1];

    float ax = 0.f, ay = 0.f;
    for (int e0 = start; e0 < end; e0 += 32) {
        int idx = e0 + lane;
        int s = 0; float w = 0.f;
        if (idx < end) { s = g_col[idx]; w = g_dinv[s]; }
        int cnt = min(32, end - e0);
        for (int j = 0; j < cnt; j++) {
            int   sj = __shfl_sync(0xffffffffu, s, j);
            float wj = __shfl_sync(0xffffffffu, w, j);
            if (act) {
                float2 v = *(const float2*)&g_xw2[(size_t)sj * F_OUT + lane * 2];
                ax += wj * v.x;
                ay += wj * v.y;
            }
        }
    }
    float dn = g_dinv[n];
    float o0 = 0.f, o1 = 0.f;
    if (act) {
        float2 sv = *(const float2*)&g_xw2[(size_t)n * F_OUT + lane * 2];
        o0 = dn * (ax + dn * sv.x) + b2[lane * 2];
        o1 = dn * (ay + dn * sv.y) + b2[lane * 2 + 1];
    }
    // warp log-softmax over the 40 values
    float m = act ? fmaxf(o0, o1) : -3.402823e38f;
    #pragma unroll
    for (int off = 16; off > 0; off >>= 1)
        m = fmaxf(m, __shfl_xor_sync(0xffffffffu, m, off));
    float s = act ? (expf(o0 - m) + expf(o1 - m)) : 0.f;
    #pragma unroll
    for (int off = 16; off > 0; off >>= 1)
        s += __shfl_xor_sync(0xffffffffu, s, off);
    float lse = logf(s) + m;
    if (act) {
        size_t base = (size_t)n * F_OUT + lane * 2;
        out[base]     = o0 - lse;              // log_softmax
        out[base + 1] = o1 - lse;
        if (logits_off > 0) {
            out[(size_t)logits_off + base]     = o0;  // logits
            out[(size_t)logits_off + base + 1] = o1;
        }
    }
}

// ---------------------------------------------------------------------------
extern "C" void kernel_launch(void* const* d_in, const int* in_sizes, int n_in,
                              void* d_out, int out_size) {
    const float* x  = (const float*)d_in[0];
    const int*   ei = (const int*)d_in[1];     // int32 (JAX x64 disabled)
    const float* W1 = (const float*)d_in[2];
    const float* b1 = (const float*)d_in[3];
    const float* W2 = (const float*)d_in[4];
    const float* b2 = (const float*)d_in[5];
    float* out = (float*)d_out;

    int N = in_sizes[0] / F_IN;    // 100000
    int E = in_sizes[1] / 2;       // 1600000
    int NB = (N + 1023) / 1024;    // 98 scan blocks

    long long logits_off = ((long long)out_size >= 2LL * N * F_OUT)
                         ? (long long)N * F_OUT : 0;

    // graph preprocessing
    k_zero<<<(N + 255) / 256, 256>>>(N);
    k_deg<<<(E + 255) / 256, 256>>>(ei, E);
    k_dinv<<<(N + 255) / 256, 256>>>(N);
    k_scan_blocks<<<NB, 1024>>>(N);
    k_scan_partials<<<1, 128>>>(NB);
    k_scan_add<<<(N + 255) / 256, 256>>>(N, E);
    k_fill_col<<<(E + 255) / 256, 256>>>(ei, E);

    // layer 1
    k_gemm1_tf32<<<(N + G1_BM - 1) / G1_BM, 256>>>(x, W1, N);
    k_agg1<<<(N * 32 + 255) / 256, 256>>>(b1, N);

    // layer 2
    k_gemm2<<<4096, 256>>>(W2, N);
    k_agg2<<<(N * 32 + 255) / 256, 256>>>(b2, out, N, logits_off);
}

// round 6
// speedup vs baseline: 1.6279x; 1.3291x over previous
#include <cuda_runtime.h>
#include <math.h>
#include <stdint.h>

#define N_NODES 100000
#define N_EDGES 1600000
#define F_IN    500
#define F_HID   64
#define F_OUT   40

// ---------------- scratch (static device globals; no allocations) ----------
__device__ float g_xw1[N_NODES * F_HID];     // X @ W1
__device__ float g_xw2[N_NODES * F_OUT];     // relu(conv1) @ W2
__device__ float g_w1t[F_IN * F_HID];        // W1 pre-converted to tf32 bits
__device__ float g_dinv[N_NODES];
__device__ int   g_deg [N_NODES];
__device__ int   g_cnt [N_NODES];
__device__ int   g_rowptr[N_NODES + 1];
__device__ int   g_col[N_EDGES];
__device__ int   g_blocksum[128];
__device__ int   g_blockoff[128];

__device__ __forceinline__ uint32_t f2tf32(float x) {
    uint32_t r;
    asm("cvt.rna.tf32.f32 %0, %1;" : "=r"(r) : "f"(x));
    return r;
}

// ---------------- init: zero counters + convert W1 to tf32 -----------------
__global__ void k_init(const float* __restrict__ W1, int n) {
    int i = blockIdx.x * blockDim.x + threadIdx.x;
    if (i < n) { g_deg[i] = 0; g_cnt[i] = 0; }
    if (i < F_IN * F_HID) g_w1t[i] = __uint_as_float(f2tf32(W1[i]));
}

// edge_index is int32 (JAX downcasts int64 without x64 mode)
__global__ void k_deg(const int* __restrict__ ei, int E) {
    int i = blockIdx.x * blockDim.x + threadIdx.x;
    if (i < E) {
        int dst = ei[E + i];
        if (dst >= 0 && dst < N_NODES) atomicAdd(&g_deg[dst], 1);
    }
}

// block-local exclusive scan of g_deg into g_rowptr (+ fused dinv)
__global__ void k_scan_blocks(int n) {
    __shared__ int buf[1024];
    int tid = threadIdx.x;
    int gid = blockIdx.x * 1024 + tid;
    int v = (gid < n) ? g_deg[gid] : 0;
    if (gid < n) g_dinv[gid] = rsqrtf((float)(v + 1));   // +1 self loop
    buf[tid] = v;
    __syncthreads();
    #pragma unroll
    for (int off = 1; off < 1024; off <<= 1) {
        int t = (tid >= off) ? buf[tid - off] : 0;
        __syncthreads();
        buf[tid] += t;
        __syncthreads();
    }
    if (gid < n) g_rowptr[gid] = buf[tid] - v;  // exclusive
    if (tid == 1023) g_blocksum[blockIdx.x] = buf[1023];
}

__global__ void k_scan_partials(int nb) {
    __shared__ int buf[128];
    int tid = threadIdx.x;  // 128 threads
    int v = (tid < nb) ? g_blocksum[tid] : 0;
    buf[tid] = v;
    __syncthreads();
    #pragma unroll
    for (int off = 1; off < 128; off <<= 1) {
        int t = (tid >= off) ? buf[tid - off] : 0;
        __syncthreads();
        buf[tid] += t;
        __syncthreads();
    }
    g_blockoff[tid] = buf[tid] - v;  // exclusive
}

__global__ void k_scan_add(int n, int E) {
    int gid = blockIdx.x * blockDim.x + threadIdx.x;
    if (gid < n) g_rowptr[gid] += g_blockoff[gid >> 10];
    if (gid == 0) g_rowptr[n] = E;
}

__global__ void k_fill_col(const int* __restrict__ ei, int E) {
    int i = blockIdx.x * blockDim.x + threadIdx.x;
    if (i < E) {
        int src = ei[i];
        int dst = ei[E + i];
        if (dst >= 0 && dst < N_NODES && src >= 0 && src < N_NODES) {
            int p = g_rowptr[dst] + atomicAdd(&g_cnt[dst], 1);
            g_col[p] = src;
        }
    }
}

// ---------------- GEMM1 (tf32 tensor cores, cp.async pipelined) ------------
// X[M,500] @ W1t[500,64] -> g_xw1.  BM=128, BN=64, BK=32, 2-stage cp.async.
// 8 warps in 4x2; each warp computes 32x32 via m16n8k8 tf32 mma.

__device__ __forceinline__ void mma_tf32(float* c, const uint32_t* a, const uint32_t* b) {
    asm volatile(
        "mma.sync.aligned.m16n8k8.row.col.f32.tf32.tf32.f32 "
        "{%0,%1,%2,%3}, {%4,%5,%6,%7}, {%8,%9}, {%0,%1,%2,%3};"
        : "+f"(c[0]), "+f"(c[1]), "+f"(c[2]), "+f"(c[3])
        : "r"(a[0]), "r"(a[1]), "r"(a[2]), "r"(a[3]), "r"(b[0]), "r"(b[1]));
}

__device__ __forceinline__ void cp16(uint32_t smem_addr, const void* gptr, int src_bytes) {
    asm volatile("cp.async.cg.shared.global [%0], [%1], 16, %2;"
                 :: "r"(smem_addr), "l"(gptr), "r"(src_bytes));
}

#define G1_BM 128
#define G1_BK 32
#define G1_SA 36    // As row stride (floats): (4g+tg)%32 distinct -> conflict-free
#define G1_SB 72    // Bs row stride (floats): (8tg+g)%32 distinct -> conflict-free
#define G1_A_STAGE (G1_BM * G1_SA)
#define G1_B_STAGE (G1_BK * G1_SB)
#define G1_SMEM_BYTES ((2 * G1_A_STAGE + 2 * G1_B_STAGE) * 4)

extern __shared__ float g1_smem[];

__global__ __launch_bounds__(256) void k_gemm1_tf32(const float* __restrict__ X,
                                                    int M) {
    float* As = g1_smem;                       // [2][128][36]  row-major (m,k)
    float* Bs = g1_smem + 2 * G1_A_STAGE;      // [2][32][72]   (k,n)
    uint32_t as_u = (uint32_t)__cvta_generic_to_shared(As);
    uint32_t bs_u = (uint32_t)__cvta_generic_to_shared(Bs);

    int tid  = threadIdx.x;
    int lane = tid & 31, warp = tid >> 5;
    int warp_m = warp >> 1;        // 0..3 -> 32 rows each
    int warp_n = warp & 1;         // 0..1 -> 32 cols each
    int g  = lane >> 2;            // 0..7
    int tg = lane & 3;             // 0..3
    int row0 = blockIdx.x * G1_BM;

    float c[2][4][4] = {};

    // stage loader: A 1024 chunks (4/thread), B 512 chunks (2/thread)
    auto load_stage = [&](int st, int k0) {
        #pragma unroll
        for (int i = 0; i < 4; i++) {
            int s  = tid + i * 256;
            int r  = s >> 3;             // 0..127
            int kq = s & 7;              // 16B chunk in k
            int k  = k0 + kq * 4;
            int grow = row0 + r;
            bool v = (grow < M) && (k < F_IN);      // 500 % 4 == 0: chunk all-or-nothing
            const float* gp = X + (size_t)(v ? grow : 0) * F_IN + (v ? k : 0);
            cp16(as_u + (uint32_t)(((st * G1_BM + r) * G1_SA + kq * 4) * 4), gp, v ? 16 : 0);
        }
        #pragma unroll
        for (int i = 0; i < 2; i++) {
            int s  = tid + i * 256;
            int kr = s >> 4;             // 0..31
            int nq = s & 15;             // 16B chunk in n
            int k  = k0 + kr;
            bool v = (k < F_IN);
            const float* gp = g_w1t + (size_t)(v ? k : 0) * F_HID + nq * 4;
            cp16(bs_u + (uint32_t)(((st * G1_BK + kr) * G1_SB + nq * 4) * 4), gp, v ? 16 : 0);
        }
        asm volatile("cp.async.commit_group;");
    };

    load_stage(0, 0);

    #pragma unroll 1
    for (int it = 0; it < 16; it++) {
        if (it < 15) {
            load_stage((it + 1) & 1, (it + 1) * G1_BK);
            asm volatile("cp.async.wait_group 1;");
        } else {
            asm volatile("cp.async.wait_group 0;");
        }
        __syncthreads();

        const float* A = As + (it & 1) * G1_A_STAGE;
        const float* B = Bs + (it & 1) * G1_B_STAGE;
        int m0 = warp_m * 32;
        int n0 = warp_n * 32;
        #pragma unroll
        for (int kb = 0; kb < G1_BK; kb += 8) {
            uint32_t a[2][4], b[4][2];
            #pragma unroll
            for (int mf = 0; mf < 2; mf++) {
                int r = m0 + mf * 16 + g;
                a[mf][0] = f2tf32(A[r * G1_SA + kb + tg]);
                a[mf][1] = f2tf32(A[(r + 8) * G1_SA + kb + tg]);
                a[mf][2] = f2tf32(A[r * G1_SA + kb + tg + 4]);
                a[mf][3] = f2tf32(A[(r + 8) * G1_SA + kb + tg + 4]);
            }
            #pragma unroll
            for (int nf = 0; nf < 4; nf++) {
                int n = n0 + nf * 8 + g;
                b[nf][0] = __float_as_uint(B[(kb + tg) * G1_SB + n]);      // pre-converted
                b[nf][1] = __float_as_uint(B[(kb + tg + 4) * G1_SB + n]);
            }
            #pragma unroll
            for (int mf = 0; mf < 2; mf++)
                #pragma unroll
                for (int nf = 0; nf < 4; nf++)
                    mma_tf32(c[mf][nf], a[mf], b[nf]);
        }
        __syncthreads();
    }

    // ---- epilogue ----
    #pragma unroll
    for (int mf = 0; mf < 2; mf++) {
        int r0 = row0 + warp_m * 32 + mf * 16 + g;
        int r1 = r0 + 8;
        #pragma unroll
        for (int nf = 0; nf < 4; nf++) {
            int col = warp_n * 32 + nf * 8 + tg * 2;
            if (r0 < M)
                *(float2*)&g_xw1[(size_t)r0 * F_HID + col] =
                    make_float2(c[mf][nf][0], c[mf][nf][1]);
            if (r1 < M)
                *(float2*)&g_xw1[(size_t)r1 * F_HID + col] =
                    make_float2(c[mf][nf][2], c[mf][nf][3]);
        }
    }
}

// ------- fused: agg layer 1 (F=64) + bias + relu + GEMM2 -> g_xw2 ----------
// warp per node (grid-stride); h row lives in smem, W2 cached in smem.
__global__ __launch_bounds__(256) void k_agg1_gemm2(const float* __restrict__ b1,
                                                    const float* __restrict__ W2,
                                                    int N) {
    __shared__ float W2s[F_HID * F_OUT];   // 10.2 KB
    __shared__ float hrow[8][F_HID];       // 2 KB
    int tid = threadIdx.x;
    for (int i = tid; i < F_HID * F_OUT; i += 256) W2s[i] = W2[i];
    __syncthreads();
    int lane = tid & 31, warp = tid >> 5;
    float bx = b1[lane * 2], by = b1[lane * 2 + 1];
    int stride = gridDim.x * 8;

    for (int n = blockIdx.x * 8 + warp; n < N; n += stride) {
        int start = g_rowptr[n], end = g_rowptr[n + 1];
        float ax = 0.f, ay = 0.f;
        for (int e0 = start; e0 < end; e0 += 32) {
            int idx = e0 + lane;
            int s = 0; float w = 0.f;
            if (idx < end) { s = g_col[idx]; w = g_dinv[s]; }
            int cnt = min(32, end - e0);
            #pragma unroll 4
            for (int j = 0; j < cnt; j++) {
                int   sj = __shfl_sync(0xffffffffu, s, j);
                float wj = __shfl_sync(0xffffffffu, w, j);
                float2 v = *(const float2*)&g_xw1[(size_t)sj * F_HID + lane * 2];
                ax += wj * v.x;
                ay += wj * v.y;
            }
        }
        float dn = g_dinv[n];
        float2 sv = *(const float2*)&g_xw1[(size_t)n * F_HID + lane * 2];
        float ox = fmaxf(dn * (ax + dn * sv.x) + bx, 0.f);
        float oy = fmaxf(dn * (ay + dn * sv.y) + by, 0.f);
        hrow[warp][lane * 2]     = ox;
        hrow[warp][lane * 2 + 1] = oy;
        __syncwarp();
        float a0 = 0.f, a1 = 0.f;
        #pragma unroll
        for (int k = 0; k < F_HID; k++) {
            float hk = hrow[warp][k];
            a0 += hk * W2s[k * F_OUT + lane];
            if (lane < 8) a1 += hk * W2s[k * F_OUT + 32 + lane];
        }
        g_xw2[(size_t)n * F_OUT + lane] = a0;
        if (lane < 8) g_xw2[(size_t)n * F_OUT + 32 + lane] = a1;
        __syncwarp();
    }
}

// ------- agg layer 2 (F=40) + bias + fused log_softmax -> d_out ------------
__global__ __launch_bounds__(256) void k_agg2(const float* __restrict__ b2,
                                              float* __restrict__ out, int N,
                                              long long logits_off) {
    int warp = (blockIdx.x * blockDim.x + threadIdx.x) >> 5;
    int lane = threadIdx.x & 31;
    if (warp >= N) return;
    int n = warp;
    bool act = lane < 20;   // lanes 0..19 each own 2 of the 40 features
    int start = g_rowptr[n], end = g_rowptr[n + 1];

    float ax = 0.f, ay = 0.f;
    for (int e0 = start; e0 < end; e0 += 32) {
        int idx = e0 + lane;
        int s = 0; float w = 0.f;
        if (idx < end) { s = g_col[idx]; w = g_dinv[s]; }
        int cnt = min(32, end - e0);
        #pragma unroll 4
        for (int j = 0; j < cnt; j++) {
            int   sj = __shfl_sync(0xffffffffu, s, j);
            float wj = __shfl_sync(0xffffffffu, w, j);
            if (act) {
                float2 v = *(const float2*)&g_xw2[(size_t)sj * F_OUT + lane * 2];
                ax += wj * v.x;
                ay += wj * v.y;
            }
        }
    }
    float dn = g_dinv[n];
    float o0 = 0.f, o1 = 0.f;
    if (act) {
        float2 sv = *(const float2*)&g_xw2[(size_t)n * F_OUT + lane * 2];
        o0 = dn * (ax + dn * sv.x) + b2[lane * 2];
        o1 = dn * (ay + dn * sv.y) + b2[lane * 2 + 1];
    }
    // warp log-softmax over the 40 values
    float m = act ? fmaxf(o0, o1) : -3.402823e38f;
    #pragma unroll
    for (int off = 16; off > 0; off >>= 1)
        m = fmaxf(m, __shfl_xor_sync(0xffffffffu, m, off));
    float s = act ? (expf(o0 - m) + expf(o1 - m)) : 0.f;
    #pragma unroll
    for (int off = 16; off > 0; off >>= 1)
        s += __shfl_xor_sync(0xffffffffu, s, off);
    float lse = logf(s) + m;
    if (act) {
        size_t base = (size_t)n * F_OUT + lane * 2;
        out[base]     = o0 - lse;              // log_softmax
        out[base + 1] = o1 - lse;
        if (logits_off > 0) {
            out[(size_t)logits_off + base]     = o0;  // logits
            out[(size_t)logits_off + base + 1] = o1;
        }
    }
}

// ---------------------------------------------------------------------------
extern "C" void kernel_launch(void* const* d_in, const int* in_sizes, int n_in,
                              void* d_out, int out_size) {
    const float* x  = (const float*)d_in[0];
    const int*   ei = (const int*)d_in[1];     // int32 (JAX x64 disabled)
    const float* W1 = (const float*)d_in[2];
    const float* b1 = (const float*)d_in[3];
    const float* W2 = (const float*)d_in[4];
    const float* b2 = (const float*)d_in[5];
    float* out = (float*)d_out;

    int N = in_sizes[0] / F_IN;    // 100000
    int E = in_sizes[1] / 2;       // 1600000
    int NB = (N + 1023) / 1024;    // 98 scan blocks

    long long logits_off = ((long long)out_size >= 2LL * N * F_OUT)
                         ? (long long)N * F_OUT : 0;

    // not a stream op; idempotent and legal during graph capture
    cudaFuncSetAttribute(k_gemm1_tf32,
                         cudaFuncAttributeMaxDynamicSharedMemorySize,
                         G1_SMEM_BYTES);

    // graph preprocessing
    k_init<<<(N + 255) / 256, 256>>>(W1, N);
    k_deg<<<(E + 255) / 256, 256>>>(ei, E);
    k_scan_blocks<<<NB, 1024>>>(N);
    k_scan_partials<<<1, 128>>>(NB);
    k_scan_add<<<(N + 255) / 256, 256>>>(N, E);
    k_fill_col<<<(E + 255) / 256, 256>>>(ei, E);

    // layer 1 (+ fused layer-2 transform)
    k_gemm1_tf32<<<(N + G1_BM - 1) / G1_BM, 256, G1_SMEM_BYTES>>>(x, N);
    k_agg1_gemm2<<<2048, 256>>>(b1, W2, N);

    // layer 2 aggregation + softmax
    k_agg2<<<(N * 32 + 255) / 256, 256>>>(b2, out, N, logits_off);
}